// round 1
// baseline (speedup 1.0000x reference)
#include <cuda_runtime.h>

// ---------------------------------------------------------------------------
// ClientBackbone: 4x (conv1x1 [+ bilinear 2x upsample] [+ block shuffle])
// plus passthrough copies.
//
// Outputs (float32, concatenated):
//   x_final : off 0         len 32768      (copy of d_in[4])
//   aux1    : off 32768     len 12845056   (shuffle(upsample2x(conv(f1,cw1))))
//   aux2    : off 12877824  len 6422528    (upsample2x(conv(f2,cw2)))
//   aux3    : off 19300352  len 3211264    (upsample2x(conv(f3,cw3)))
//   aux4    : off 22511616  len 1605632    (conv(f4,cw4), 7->7 resize = id)
//   w1..w4  : off 24117248/24317952/24418304/24468480 (copies)
//
// Conv and bilinear-upsample commute (both linear), so convs run at source
// resolution (4x fewer FLOPs for layers 1-3) and the upsample runs after.
// ---------------------------------------------------------------------------

static constexpr int BATCH = 64;

// Scratch for conv outputs at source resolution (allocation-free rule:
// __device__ globals).
__device__ float g1_scratch[BATCH * 64 * 28 * 28];    // 3,211,264
__device__ float g2_scratch[BATCH * 128 * 14 * 14];   // 1,605,632
__device__ float g3_scratch[BATCH * 256 * 7 * 7];     //   802,816

// ---------------------------------------------------------------------------
// conv1x1: out[b, m, p] = sum_k w[m, k] * f[b, k, p] + bias[m]
// Treated as GEMM over flat n = b*P + p (N = 64*P, always divisible by 64).
// 64x64 output tile per block, K-tile 16, 4x4 microtile per thread.
// ---------------------------------------------------------------------------
template <int M, int K, int P>
__global__ __launch_bounds__(256) void conv1x1_kernel(
    const float* __restrict__ f, const float* __restrict__ w,
    const float* __restrict__ bias, float* __restrict__ out)
{
    __shared__ float ws[16][68];   // ws[k][m], padded row (68*4B = 16B aligned)
    __shared__ float fs[16][64];   // fs[k][n]
    __shared__ int   foff[64];     // per-n input base offset (b*K*P + p)
    __shared__ int   ooff[64];     // per-n output base offset (b*M*P + p)

    const int tid = threadIdx.x;
    const int n0 = blockIdx.x * 64;
    const int m0 = blockIdx.y * 64;

    if (tid < 64) {
        int nn = n0 + tid;
        int b = nn / P;
        int p = nn - b * P;
        foff[tid] = b * (K * P) + p;
        ooff[tid] = b * (M * P) + p;
    }
    __syncthreads();

    const int tm = tid >> 4;   // 0..15 (m groups of 4)
    const int tp = tid & 15;   // 0..15 (n groups of 4)

    float acc[4][4];
#pragma unroll
    for (int i = 0; i < 4; i++)
#pragma unroll
        for (int j = 0; j < 4; j++) acc[i][j] = 0.0f;

    for (int k0 = 0; k0 < K; k0 += 16) {
        // Load W tile: consecutive threads walk k (coalesced 64B segments).
#pragma unroll
        for (int i = 0; i < 4; i++) {
            int e = tid + 256 * i;
            ws[e & 15][e >> 4] = w[(m0 + (e >> 4)) * K + (k0 + (e & 15))];
        }
        // Load F tile: consecutive threads walk n (coalesced within batch).
#pragma unroll
        for (int i = 0; i < 4; i++) {
            int e = tid + 256 * i;
            fs[e >> 6][e & 63] = f[foff[e & 63] + (k0 + (e >> 6)) * P];
        }
        __syncthreads();

#pragma unroll
        for (int k = 0; k < 16; k++) {
            float4 wv = *reinterpret_cast<const float4*>(&ws[k][tm * 4]);
            float4 fv = *reinterpret_cast<const float4*>(&fs[k][tp * 4]);
            acc[0][0] += wv.x * fv.x; acc[0][1] += wv.x * fv.y;
            acc[0][2] += wv.x * fv.z; acc[0][3] += wv.x * fv.w;
            acc[1][0] += wv.y * fv.x; acc[1][1] += wv.y * fv.y;
            acc[1][2] += wv.y * fv.z; acc[1][3] += wv.y * fv.w;
            acc[2][0] += wv.z * fv.x; acc[2][1] += wv.z * fv.y;
            acc[2][2] += wv.z * fv.z; acc[2][3] += wv.z * fv.w;
            acc[3][0] += wv.w * fv.x; acc[3][1] += wv.w * fv.y;
            acc[3][2] += wv.w * fv.z; acc[3][3] += wv.w * fv.w;
        }
        __syncthreads();
    }

#pragma unroll
    for (int im = 0; im < 4; im++) {
        int m = m0 + tm * 4 + im;
        float bv = bias[m];
#pragma unroll
        for (int ip = 0; ip < 4; ip++) {
            out[ooff[tp * 4 + ip] + m * P] = acc[im][ip] + bv;
        }
    }
}

// ---------------------------------------------------------------------------
// Bilinear 2x upsample, half-pixel (align_corners=False), clamped edges.
// src = (dst + 0.5)/2 - 0.5  =>  i0 = (dst-1)>>1 (clamped), frac = dst odd ?
// 0.25 : 0.75. For SHUF (aux1): source channel = perms[blk*64 + c],
// blk = (y/28)*2 + (x/28).
// ---------------------------------------------------------------------------
template <int C, int SI, bool SHUF>
__global__ __launch_bounds__(256) void upsample2x_kernel(
    const float* __restrict__ g, float* __restrict__ out,
    const int* __restrict__ perms)
{
    constexpr int S = SI * 2;
    constexpr int TOTAL = BATCH * C * S * S;
    int t = blockIdx.x * 256 + threadIdx.x;
    if (t >= TOTAL) return;

    int x = t % S;
    int y = (t / S) % S;
    int c = (t / (S * S)) % C;
    int b = t / (S * S * C);

    int cs = c;
    if (SHUF) {
        int blk = ((y >= 28) ? 2 : 0) + ((x >= 28) ? 1 : 0);
        cs = perms[blk * 64 + c];
    }
    const float* gp = g + (b * C + cs) * (SI * SI);

    int iy = (y - 1) >> 1;                 // arithmetic shift: y=0 -> -1
    int iy0 = iy < 0 ? 0 : iy;
    int iy1 = (iy + 1 > SI - 1) ? SI - 1 : iy + 1;
    float fy = (y & 1) ? 0.25f : 0.75f;

    int ix = (x - 1) >> 1;
    int ix0 = ix < 0 ? 0 : ix;
    int ix1 = (ix + 1 > SI - 1) ? SI - 1 : ix + 1;
    float fx = (x & 1) ? 0.25f : 0.75f;

    float v00 = gp[iy0 * SI + ix0];
    float v01 = gp[iy0 * SI + ix1];
    float v10 = gp[iy1 * SI + ix0];
    float v11 = gp[iy1 * SI + ix1];

    float top = v00 + fx * (v01 - v00);
    float bot = v10 + fx * (v11 - v10);
    out[t] = top + fy * (bot - top);
}

// ---------------------------------------------------------------------------
// kernel_launch
// ---------------------------------------------------------------------------
extern "C" void kernel_launch(void* const* d_in, const int* in_sizes, int n_in,
                              void* d_out, int out_size)
{
    (void)in_sizes; (void)n_in; (void)out_size;

    const float* f1      = (const float*)d_in[0];
    const float* f2      = (const float*)d_in[1];
    const float* f3      = (const float*)d_in[2];
    const float* f4      = (const float*)d_in[3];
    const float* x_final = (const float*)d_in[4];
    const float* cw1     = (const float*)d_in[5];
    const float* cb1     = (const float*)d_in[6];
    const float* cw2     = (const float*)d_in[7];
    const float* cb2     = (const float*)d_in[8];
    const float* cw3     = (const float*)d_in[9];
    const float* cb3     = (const float*)d_in[10];
    const float* cw4     = (const float*)d_in[11];
    const float* cb4     = (const float*)d_in[12];
    const float* w1      = (const float*)d_in[13];
    const float* w2      = (const float*)d_in[14];
    const float* w3      = (const float*)d_in[15];
    const float* w4      = (const float*)d_in[16];
    const int*   perms   = (const int*)  d_in[17];

    float* out = (float*)d_out;

    float *g1, *g2, *g3;
    cudaGetSymbolAddress((void**)&g1, g1_scratch);
    cudaGetSymbolAddress((void**)&g2, g2_scratch);
    cudaGetSymbolAddress((void**)&g3, g3_scratch);

    // Output offsets (floats)
    constexpr long OFF_XF   = 0;
    constexpr long OFF_AUX1 = 32768;
    constexpr long OFF_AUX2 = 12877824;
    constexpr long OFF_AUX3 = 19300352;
    constexpr long OFF_AUX4 = 22511616;
    constexpr long OFF_W1   = 24117248;
    constexpr long OFF_W2   = 24317952;
    constexpr long OFF_W3   = 24418304;
    constexpr long OFF_W4   = 24468480;

    // Passthrough copies (D2D async: graph-capturable)
    cudaMemcpyAsync(out + OFF_XF, x_final, 32768 * sizeof(float),
                    cudaMemcpyDeviceToDevice, 0);
    cudaMemcpyAsync(out + OFF_W1, w1, 200704 * sizeof(float),
                    cudaMemcpyDeviceToDevice, 0);
    cudaMemcpyAsync(out + OFF_W2, w2, 100352 * sizeof(float),
                    cudaMemcpyDeviceToDevice, 0);
    cudaMemcpyAsync(out + OFF_W3, w3, 50176 * sizeof(float),
                    cudaMemcpyDeviceToDevice, 0);
    cudaMemcpyAsync(out + OFF_W4, w4, 25088 * sizeof(float),
                    cudaMemcpyDeviceToDevice, 0);

    // Convs at source resolution. grid.x = 64*P/64 = P-ish flat-N tiles.
    conv1x1_kernel<64, 64, 784><<<dim3(784, 1), 256>>>(f1, cw1, cb1, g1);
    conv1x1_kernel<128, 128, 196><<<dim3(196, 2), 256>>>(f2, cw2, cb2, g2);
    conv1x1_kernel<256, 128, 49><<<dim3(49, 4), 256>>>(f3, cw3, cb3, g3);
    // aux4: no upsample (7 -> 7), write output region directly.
    conv1x1_kernel<512, 512, 49><<<dim3(49, 8), 256>>>(f4, cw4, cb4,
                                                       out + OFF_AUX4);

    // Upsamples (aux1 fused with the per-block channel shuffle).
    upsample2x_kernel<64, 28, true><<<50176, 256>>>(g1, out + OFF_AUX1, perms);
    upsample2x_kernel<128, 14, false><<<25088, 256>>>(g2, out + OFF_AUX2, nullptr);
    upsample2x_kernel<256, 7, false><<<12544, 256>>>(g3, out + OFF_AUX3, nullptr);
}